// round 1
// baseline (speedup 1.0000x reference)
#include <cuda_runtime.h>
#include <cuda_bf16.h>
#include <cstdint>

#define IMG_N_ANC   8649      // 31*31*9
#define SORT_N      16384
#define PRE_NMS     6000
#define POST_NMS    1500
#define IOU_THR     0.7f
#define BATCH       16

// ---- shared memory layout (bytes, within dynamic smem) ----
// [0, 131072)          : u64 sort keys (16384)            -- sort phase only
// [0, 48000)           : top-6000 keys survive into decode phase
// [48000 .. )          : NMS arrays (overlap tail of sort buffer; safe because
//                        only the first 6000 keys are read after the sort)
#define OFF_Y1    48000
#define OFF_X1    72000
#define OFF_Y2    96000
#define OFF_X2    120000
#define OFF_AREA  144000
#define OFF_SC    168000
#define OFF_SUPP  192000            // 6000 bytes (u8)
#define OFF_PIVOT 198000            // int
#define SMEM_TOTAL 198016

__global__ __launch_bounds__(1024, 1)
void roibbox_kernel(const float* __restrict__ deltas,   // [B,31,31,36] == [B,N,4]
                    const float* __restrict__ probs,    // [B,31,31,9]  == [B,N]
                    const float* __restrict__ anchors,  // [N,4]
                    float* __restrict__ out)            // [B,1500,4] ++ [B,1500]
{
    extern __shared__ char smem[];
    unsigned long long* keys = (unsigned long long*)smem;
    float* sy1 = (float*)(smem + OFF_Y1);
    float* sx1 = (float*)(smem + OFF_X1);
    float* sy2 = (float*)(smem + OFF_Y2);
    float* sx2 = (float*)(smem + OFF_X2);
    float* sar = (float*)(smem + OFF_AREA);
    float* ssc = (float*)(smem + OFF_SC);
    unsigned char* supp = (unsigned char*)(smem + OFF_SUPP);
    int* s_pivot = (int*)(smem + OFF_PIVOT);

    const int b   = blockIdx.x;
    const int tid = threadIdx.x;
    const int nt  = blockDim.x;

    // ---------------- phase 1: build keys ----------------
    const float* pb = probs + (size_t)b * IMG_N_ANC;
    for (int i = tid; i < SORT_N; i += nt) {
        unsigned long long k = 0ull;
        if (i < IMG_N_ANC) {
            unsigned int bits = __float_as_uint(pb[i]);   // scores in [0,1): bit order == value order
            k = ((unsigned long long)bits << 32) | (unsigned long long)(0xFFFFFFFFu - (unsigned)i);
        }
        keys[i] = k;
    }
    __syncthreads();

    // ---------------- phase 2: descending bitonic sort (exact) ----------------
    for (int k = 2; k <= SORT_N; k <<= 1) {
        for (int j = k >> 1; j > 0; j >>= 1) {
            for (int i = tid; i < SORT_N; i += nt) {
                int ixj = i ^ j;
                if (ixj > i) {
                    unsigned long long a = keys[i];
                    unsigned long long c = keys[ixj];
                    bool dir = ((i & k) == 0);          // descending overall
                    if ((a < c) == dir) { keys[i] = c; keys[ixj] = a; }
                }
            }
            __syncthreads();
        }
    }

    // ---------------- phase 3: decode top-6000 boxes into smem ----------------
    const float* db = deltas + (size_t)b * IMG_N_ANC * 4;
    for (int t = tid; t < PRE_NMS; t += nt) {
        unsigned long long key = keys[t];
        unsigned int idx = 0xFFFFFFFFu - (unsigned int)(key & 0xFFFFFFFFull);
        float score = __uint_as_float((unsigned int)(key >> 32));

        float a0 = anchors[idx * 4 + 0];
        float a1 = anchors[idx * 4 + 1];
        float a2 = anchors[idx * 4 + 2];
        float a3 = anchors[idx * 4 + 3];
        float d0 = db[(size_t)idx * 4 + 0] * 0.1f;
        float d1 = db[(size_t)idx * 4 + 1] * 0.1f;
        float d2 = db[(size_t)idx * 4 + 2] * 0.2f;
        float d3 = db[(size_t)idx * 4 + 3] * 0.2f;

        float anc_h = a2 - a0;
        float anc_w = a3 - a1;
        float ctr_y = a0 + 0.5f * anc_h;
        float ctr_x = a1 + 0.5f * anc_w;
        float bh = expf(d2) * anc_h;
        float bw = expf(d3) * anc_w;
        float bcy = d0 * anc_h + ctr_y;
        float bcx = d1 * anc_w + ctr_x;
        float y1 = bcy - 0.5f * bh;
        float x1 = bcx - 0.5f * bw;
        float y2 = y1 + bh;
        float x2 = x1 + bw;

        sy1[t] = y1; sx1[t] = x1; sy2[t] = y2; sx2[t] = x2;
        sar[t] = (y2 - y1) * (x2 - x1);
        ssc[t] = score;
        supp[t] = 0;
    }

    // zero this batch's output slice (d_out is poisoned)
    float* ob = out + (size_t)b * POST_NMS * 4;
    float* os = out + (size_t)BATCH * POST_NMS * 4 + (size_t)b * POST_NMS;
    for (int t = tid; t < POST_NMS * 4; t += nt) ob[t] = 0.0f;
    for (int t = tid; t < POST_NMS; t += nt)     os[t] = 0.0f;
    __syncthreads();

    // ---------------- phase 4: greedy sequential NMS ----------------
    int scan = 0;   // thread 0's scan pointer
    int cnt  = 0;   // thread 0's kept count
    while (true) {
        if (tid == 0) {
            while (scan < PRE_NMS && supp[scan]) scan++;
            *s_pivot = (scan < PRE_NMS && cnt < POST_NMS) ? scan : -1;
        }
        __syncthreads();
        int p = *s_pivot;
        if (p < 0) break;

        float py1 = sy1[p], px1 = sx1[p], py2 = sy2[p], px2 = sx2[p], par = sar[p];

        if (tid == 0) {
            // write kept box at rank == cnt (clipped), and its score
            ob[cnt * 4 + 0] = fminf(fmaxf(py1, 0.0f), 1.0f);
            ob[cnt * 4 + 1] = fminf(fmaxf(px1, 0.0f), 1.0f);
            ob[cnt * 4 + 2] = fminf(fmaxf(py2, 0.0f), 1.0f);
            ob[cnt * 4 + 3] = fminf(fmaxf(px2, 0.0f), 1.0f);
            os[cnt] = ssc[p];
            cnt++;
            scan = p + 1;
        }

        for (int j = p + 1 + tid; j < PRE_NMS; j += nt) {
            if (!supp[j]) {
                float ih = fmaxf(fminf(py2, sy2[j]) - fmaxf(py1, sy1[j]), 0.0f);
                float iw = fmaxf(fminf(px2, sx2[j]) - fmaxf(px1, sx1[j]), 0.0f);
                float inter = ih * iw;
                float iou = inter / (par + sar[j] - inter + 1e-8f);
                if (iou > IOU_THR) supp[j] = 1;
            }
        }
        __syncthreads();
    }
}

extern "C" void kernel_launch(void* const* d_in, const int* in_sizes, int n_in,
                              void* d_out, int out_size) {
    const float* deltas  = (const float*)d_in[0];  // [16,31,31,36]
    const float* probs   = (const float*)d_in[1];  // [16,31,31,9]
    const float* anchors = (const float*)d_in[2];  // [8649,4]
    float* out = (float*)d_out;

    cudaFuncSetAttribute(roibbox_kernel,
                         cudaFuncAttributeMaxDynamicSharedMemorySize, SMEM_TOTAL);
    roibbox_kernel<<<BATCH, 1024, SMEM_TOTAL>>>(deltas, probs, anchors, out);
}

// round 2
// speedup vs baseline: 4.1643x; 4.1643x over previous
#include <cuda_runtime.h>
#include <cuda_bf16.h>
#include <cstdint>

#define IMG_N_ANC   8649      // 31*31*9
#define SORT_N      16384
#define PRE_NMS     6000
#define POST_NMS    1500
#define IOU_THR     0.7f
#define BATCH       16
#define NW          94        // 94 u64 words cover 6016 >= 6000 cols
#define NPAD        6016

typedef unsigned long long u64;

// ---------------- device scratch (static; no allocations) ----------------
__device__ u64   g_masks[BATCH][NW][NPAD];   // [b][col_word][row]  ~72.3 MB
__device__ float g_y1[BATCH][NPAD];
__device__ float g_x1[BATCH][NPAD];
__device__ float g_y2[BATCH][NPAD];
__device__ float g_x2[BATCH][NPAD];
__device__ float g_ar[BATCH][NPAD];
__device__ float g_sc[BATCH][NPAD];

// ================= Kernel A: sort (exact) + decode top-6000 =================
__global__ __launch_bounds__(1024, 1)
void sort_decode_kernel(const float* __restrict__ deltas,   // [B,N,4]
                        const float* __restrict__ probs,    // [B,N]
                        const float* __restrict__ anchors)  // [N,4]
{
    extern __shared__ u64 keys[];          // 16384 * 8 = 128 KB
    const int b   = blockIdx.x;
    const int tid = threadIdx.x;
    const int nt  = blockDim.x;

    const float* pb = probs + (size_t)b * IMG_N_ANC;
    for (int i = tid; i < SORT_N; i += nt) {
        u64 k = 0ull;
        if (i < IMG_N_ANC) {
            unsigned int bits = __float_as_uint(pb[i]);   // scores in [0,1): bit order == value order
            k = ((u64)bits << 32) | (u64)(0xFFFFFFFFu - (unsigned)i);
        }
        keys[i] = k;
    }
    __syncthreads();

    // descending bitonic sort, exact keys
    for (int k = 2; k <= SORT_N; k <<= 1) {
        for (int j = k >> 1; j > 0; j >>= 1) {
            for (int i = tid; i < SORT_N; i += nt) {
                int ixj = i ^ j;
                if (ixj > i) {
                    u64 a = keys[i];
                    u64 c = keys[ixj];
                    bool dir = ((i & k) == 0);
                    if ((a < c) == dir) { keys[i] = c; keys[ixj] = a; }
                }
            }
            __syncthreads();
        }
    }

    // decode top-6000 to global SoA
    const float* db = deltas + (size_t)b * IMG_N_ANC * 4;
    for (int t = tid; t < PRE_NMS; t += nt) {
        u64 key = keys[t];
        unsigned int idx = 0xFFFFFFFFu - (unsigned int)(key & 0xFFFFFFFFull);
        float score = __uint_as_float((unsigned int)(key >> 32));

        float a0 = anchors[idx * 4 + 0];
        float a1 = anchors[idx * 4 + 1];
        float a2 = anchors[idx * 4 + 2];
        float a3 = anchors[idx * 4 + 3];
        float d0 = db[(size_t)idx * 4 + 0] * 0.1f;
        float d1 = db[(size_t)idx * 4 + 1] * 0.1f;
        float d2 = db[(size_t)idx * 4 + 2] * 0.2f;
        float d3 = db[(size_t)idx * 4 + 3] * 0.2f;

        float anc_h = a2 - a0;
        float anc_w = a3 - a1;
        float ctr_y = a0 + 0.5f * anc_h;
        float ctr_x = a1 + 0.5f * anc_w;
        float bh = expf(d2) * anc_h;
        float bw = expf(d3) * anc_w;
        float bcy = d0 * anc_h + ctr_y;
        float bcx = d1 * anc_w + ctr_x;
        float y1 = bcy - 0.5f * bh;
        float x1 = bcx - 0.5f * bw;
        float y2 = y1 + bh;
        float x2 = x1 + bw;

        g_y1[b][t] = y1; g_x1[b][t] = x1;
        g_y2[b][t] = y2; g_x2[b][t] = x2;
        g_ar[b][t] = (y2 - y1) * (x2 - x1);
        g_sc[b][t] = score;
    }
}

// ================= Kernel B: forward suppression bit-matrix =================
// grid = (94 col_blocks, 94 row_blocks, 16 batches), 64 threads.
// Upper triangle only (cb >= rb). Each thread owns one row i, computes a u64
// of "i suppresses j" bits for 64 columns, writes g_masks[b][cb][i].
__global__ __launch_bounds__(64)
void iou_matrix_kernel()
{
    const int cb = blockIdx.x;
    const int rb = blockIdx.y;
    if (cb < rb) return;
    const int b   = blockIdx.z;
    const int tid = threadIdx.x;

    __shared__ float4 cbox[64];
    __shared__ float  care[64];

    const int j0 = cb * 64;
    {
        int j = j0 + tid;
        if (j < PRE_NMS) {
            cbox[tid] = make_float4(g_y1[b][j], g_x1[b][j], g_y2[b][j], g_x2[b][j]);
            care[tid] = g_ar[b][j];
        } else {
            cbox[tid] = make_float4(0.f, 0.f, 0.f, 0.f);
            care[tid] = 0.f;
        }
    }
    __syncthreads();

    const int i = rb * 64 + tid;
    if (i >= PRE_NMS) return;

    const float ry1 = g_y1[b][i], rx1 = g_x1[b][i];
    const float ry2 = g_y2[b][i], rx2 = g_x2[b][i];
    const float rar = g_ar[b][i];
    const int jmax = min(64, PRE_NMS - j0);

    u64 bits = 0ull;
    #pragma unroll 4
    for (int j = 0; j < 64; j++) {
        if (j >= jmax) break;
        float4 cb4 = cbox[j];
        float ca   = care[j];
        float ih = fmaxf(fminf(ry2, cb4.z) - fmaxf(ry1, cb4.x), 0.0f);
        float iw = fmaxf(fminf(rx2, cb4.w) - fmaxf(rx1, cb4.y), 0.0f);
        float inter = ih * iw;
        float d = rar + ca - inter + 1e-8f;      // same op order as reference
        // banded compare: exact IEEE division only near the boundary
        float diff = inter - 0.7f * d;
        bool hit;
        if (fabsf(diff) > 1e-5f * d) {
            hit = diff > 0.0f;
        } else {
            hit = (inter / d) > IOU_THR;         // matches reference rounding
        }
        if (hit && (j0 + j > i)) bits |= (1ull << j);
    }
    g_masks[b][cb][i] = bits;
}

// ================= Kernel C: greedy bit-reduce + output ====================
__global__ __launch_bounds__(256, 1)
void nms_reduce_kernel(float* __restrict__ out)
{
    const int b   = blockIdx.x;
    const int tid = threadIdx.x;

    __shared__ u64 s_rem[NW];
    __shared__ u64 s_diag[64];
    __shared__ int s_rows[64];
    __shared__ int s_nk;

    float* ob = out + (size_t)b * POST_NMS * 4;
    float* os = out + (size_t)BATCH * POST_NMS * 4 + (size_t)b * POST_NMS;

    if (tid < NW) s_rem[tid] = 0ull;
    for (int t = tid; t < POST_NMS * 4; t += 256) ob[t] = 0.0f;
    for (int t = tid; t < POST_NMS; t += 256)     os[t] = 0.0f;
    __syncthreads();

    int cnt = 0;
    for (int c = 0; c < NW; c++) {
        // load diagonal word of each row in this chunk
        if (tid < 64) {
            int row = c * 64 + tid;
            s_diag[tid] = (row < PRE_NMS) ? g_masks[b][c][row] : 0ull;
        }
        __syncthreads();

        // serial resolve of 64 rows (thread 0)
        if (tid == 0) {
            u64 rem = s_rem[c];
            int nk = 0;
            int cc = cnt;
            const int lim = min(64, PRE_NMS - c * 64);
            #pragma unroll 8
            for (int i = 0; i < 64; i++) {
                if (i < lim && cc < POST_NMS && !((rem >> i) & 1ull)) {
                    s_rows[nk] = c * 64 + i;
                    rem |= s_diag[i];
                    nk++; cc++;
                }
            }
            s_nk = nk;
        }
        __syncthreads();

        const int nk = s_nk;

        // write outputs for kept rows (rank = cnt + position)
        if (tid < nk) {
            int r    = s_rows[tid];
            int rank = cnt + tid;
            float y1 = fminf(fmaxf(g_y1[b][r], 0.0f), 1.0f);
            float x1 = fminf(fmaxf(g_x1[b][r], 0.0f), 1.0f);
            float y2 = fminf(fmaxf(g_y2[b][r], 0.0f), 1.0f);
            float x2 = fminf(fmaxf(g_x2[b][r], 0.0f), 1.0f);
            ob[rank * 4 + 0] = y1;
            ob[rank * 4 + 1] = x1;
            ob[rank * 4 + 2] = y2;
            ob[rank * 4 + 3] = x2;
            os[rank] = g_sc[b][r];
        }

        // OR kept rows' future words into removed bitmap (pair-parallel)
        const int nw = NW - 1 - c;
        if (nw > 0 && nk > 0) {
            const int pairs = nk * nw;
            for (int p = tid; p < pairs; p += 256) {
                int w = c + 1 + (p % nw);
                int r = s_rows[p / nw];
                u64 m = g_masks[b][w][r];
                if (m) atomicOr(&s_rem[w], m);
            }
        }
        cnt += nk;
        __syncthreads();
        if (cnt >= POST_NMS) break;
    }
}

// ============================== launch =====================================
extern "C" void kernel_launch(void* const* d_in, const int* in_sizes, int n_in,
                              void* d_out, int out_size) {
    const float* deltas  = (const float*)d_in[0];  // [16,31,31,36]
    const float* probs   = (const float*)d_in[1];  // [16,31,31,9]
    const float* anchors = (const float*)d_in[2];  // [8649,4]
    float* out = (float*)d_out;

    cudaFuncSetAttribute(sort_decode_kernel,
                         cudaFuncAttributeMaxDynamicSharedMemorySize, SORT_N * 8);

    sort_decode_kernel<<<BATCH, 1024, SORT_N * 8>>>(deltas, probs, anchors);
    iou_matrix_kernel<<<dim3(NW, NW, BATCH), 64>>>();
    nms_reduce_kernel<<<BATCH, 256>>>(out);
}

// round 3
// speedup vs baseline: 5.5707x; 1.3377x over previous
#include <cuda_runtime.h>
#include <cuda_bf16.h>
#include <cstdint>

#define IMG_N_ANC   8649      // 31*31*9
#define SORT_N      16384
#define SEL_N       8192
#define PRE_NMS     6000
#define POST_NMS    1500
#define IOU_THR     0.7f
#define BATCH       16
#define NW          94        // 94 u64 words cover 6016 >= 6000 cols
#define NPAD        6016
#define NBIN        2048

typedef unsigned long long u64;

// ---------------- device scratch (static; no allocations) ----------------
__device__ u64   g_masks[BATCH][NW][NPAD];   // [b][col_word][row]  ~72.3 MB
__device__ float g_y1[BATCH][NPAD];
__device__ float g_x1[BATCH][NPAD];
__device__ float g_y2[BATCH][NPAD];
__device__ float g_x2[BATCH][NPAD];
__device__ float g_ar[BATCH][NPAD];
__device__ float g_sc[BATCH][NPAD];

// ---------- descending bitonic sort, register-tiled (tile = 16 keys) -------
// n must be a power of two >= 32; nt = blockDim.x. All threads call (uniform).
__device__ __forceinline__ void bitonic_sort_desc(u64* keys, int n, int tid, int nt)
{
    const int tiles = n >> 4;

    // mega pass: k = 2..16 entirely inside each 16-key tile (no barriers)
    for (int t = tid; t < tiles; t += nt) {
        const int base = t << 4;
        u64 r[16];
        #pragma unroll
        for (int e = 0; e < 16; e++) r[e] = keys[base + e];
        #pragma unroll
        for (int k = 2; k <= 16; k <<= 1) {
            #pragma unroll
            for (int j = k >> 1; j > 0; j >>= 1) {
                #pragma unroll
                for (int e = 0; e < 16; e++) {
                    if (!(e & j)) {
                        bool dir = (((base + e) & k) == 0);
                        u64 a = r[e], c = r[e | j];
                        if ((a < c) == dir) { r[e] = c; r[e | j] = a; }
                    }
                }
            }
        }
        #pragma unroll
        for (int e = 0; e < 16; e++) keys[base + e] = r[e];
    }
    __syncthreads();

    for (int k = 32; k <= n; k <<= 1) {
        // smem stages: j = k/2 .. 16 (pair-enumerated, every iter does work)
        for (int j = k >> 1; j >= 16; j >>= 1) {
            const int half = n >> 1;
            for (int p = tid; p < half; p += nt) {
                int i  = ((p & ~(j - 1)) << 1) | (p & (j - 1));
                int ix = i + j;
                u64 a = keys[i], c = keys[ix];
                bool dir = ((i & k) == 0);
                if ((a < c) == dir) { keys[i] = c; keys[ix] = a; }
            }
            __syncthreads();
        }
        // register tail: j = 8,4,2,1 (dir uniform per tile since k >= 32)
        for (int t = tid; t < tiles; t += nt) {
            const int base = t << 4;
            const bool dir = ((base & k) == 0);
            u64 r[16];
            #pragma unroll
            for (int e = 0; e < 16; e++) r[e] = keys[base + e];
            #pragma unroll
            for (int j = 8; j > 0; j >>= 1) {
                #pragma unroll
                for (int e = 0; e < 16; e++) {
                    if (!(e & j)) {
                        u64 a = r[e], c = r[e | j];
                        if ((a < c) == dir) { r[e] = c; r[e | j] = a; }
                    }
                }
            }
            #pragma unroll
            for (int e = 0; e < 16; e++) keys[base + e] = r[e];
        }
        __syncthreads();
    }
}

// ================= Kernel A: select + sort + decode top-6000 =================
// dyn smem: keys_in[16384] u64 | keys_sort[8192] u64 | hist[2048] u32 | ctl
#define A_OFF_KSORT   (SORT_N * 8)                 // 131072
#define A_OFF_HIST    (A_OFF_KSORT + SEL_N * 8)    // 196608
#define A_OFF_CTL     (A_OFF_HIST + NBIN * 4)      // 204800
#define A_SMEM_TOTAL  (A_OFF_CTL + 16)

__global__ __launch_bounds__(1024, 1)
void sort_decode_kernel(const float* __restrict__ deltas,   // [B,N,4]
                        const float* __restrict__ probs,    // [B,N]
                        const float* __restrict__ anchors)  // [N,4]
{
    extern __shared__ char smem[];
    u64* keys_in   = (u64*)smem;
    u64* keys_sort = (u64*)(smem + A_OFF_KSORT);
    unsigned int* hist = (unsigned int*)(smem + A_OFF_HIST);
    int* s_bint  = (int*)(smem + A_OFF_CTL);
    int* s_total = (int*)(smem + A_OFF_CTL + 4);
    int* s_cnt   = (int*)(smem + A_OFF_CTL + 8);

    const int b   = blockIdx.x;
    const int tid = threadIdx.x;
    const int nt  = blockDim.x;

    // zero histogram
    for (int i = tid; i < NBIN; i += nt) hist[i] = 0u;
    if (tid == 0) *s_cnt = 0;
    __syncthreads();

    // load keys + histogram (bin = top 13 bits of the u64 key)
    const float* pb = probs + (size_t)b * IMG_N_ANC;
    for (int i = tid; i < SORT_N; i += nt) {
        u64 k = 0ull;
        if (i < IMG_N_ANC) {
            unsigned int bits = __float_as_uint(pb[i]);  // [0,1): bit order == value order
            k = ((u64)bits << 32) | (u64)(0xFFFFFFFFu - (unsigned)i);
            atomicAdd(&hist[(unsigned)(k >> 51)], 1u);
        }
        keys_in[i] = k;
    }
    __syncthreads();

    // suffix scan over bins (descending value order) — one warp
    if (tid < 32) {
        const int lane = tid;
        int part = 0;
        #pragma unroll 8
        for (int q = 0; q < 64; q++) part += (int)hist[NBIN - 1 - (lane * 64 + q)];
        // exclusive prefix over lanes (lane 0 = highest bins)
        int inc = part;
        #pragma unroll
        for (int off = 1; off < 32; off <<= 1) {
            int v = __shfl_up_sync(0xFFFFFFFFu, inc, off);
            if (lane >= off) inc += v;
        }
        int run = inc - part;   // exclusive
        for (int q = 0; q < 64; q++) {
            int v = NBIN - 1 - (lane * 64 + q);
            int h = (int)hist[v];
            run += h;
            if (run >= PRE_NMS && run - h < PRE_NMS) { *s_bint = v; *s_total = run; }
        }
    }
    __syncthreads();

    const int bint  = *s_bint;
    const int total = *s_total;
    const bool mainpath = (total <= SEL_N);

    if (mainpath) {
        // compact selected keys (order irrelevant — sort fixes it)
        for (int i = tid; i < IMG_N_ANC; i += nt) {
            u64 k = keys_in[i];
            if ((int)(unsigned)(k >> 51) >= bint) {
                int pos = atomicAdd(s_cnt, 1);
                keys_sort[pos] = k;
            }
        }
        for (int i = total + tid; i < SEL_N; i += nt) keys_sort[i] = 0ull;
        __syncthreads();
        bitonic_sort_desc(keys_sort, SEL_N, tid, nt);
    } else {
        bitonic_sort_desc(keys_in, SORT_N, tid, nt);   // fallback (never expected)
    }

    const u64* sorted = mainpath ? keys_sort : keys_in;

    // decode top-6000 to global SoA
    const float* db = deltas + (size_t)b * IMG_N_ANC * 4;
    for (int t = tid; t < PRE_NMS; t += nt) {
        u64 key = sorted[t];
        unsigned int idx = 0xFFFFFFFFu - (unsigned int)(key & 0xFFFFFFFFull);
        float score = __uint_as_float((unsigned int)(key >> 32));

        float a0 = anchors[idx * 4 + 0];
        float a1 = anchors[idx * 4 + 1];
        float a2 = anchors[idx * 4 + 2];
        float a3 = anchors[idx * 4 + 3];
        float d0 = db[(size_t)idx * 4 + 0] * 0.1f;
        float d1 = db[(size_t)idx * 4 + 1] * 0.1f;
        float d2 = db[(size_t)idx * 4 + 2] * 0.2f;
        float d3 = db[(size_t)idx * 4 + 3] * 0.2f;

        float anc_h = a2 - a0;
        float anc_w = a3 - a1;
        float ctr_y = a0 + 0.5f * anc_h;
        float ctr_x = a1 + 0.5f * anc_w;
        float bh = expf(d2) * anc_h;
        float bw = expf(d3) * anc_w;
        float bcy = d0 * anc_h + ctr_y;
        float bcx = d1 * anc_w + ctr_x;
        float y1 = bcy - 0.5f * bh;
        float x1 = bcx - 0.5f * bw;
        float y2 = y1 + bh;
        float x2 = x1 + bw;

        g_y1[b][t] = y1; g_x1[b][t] = x1;
        g_y2[b][t] = y2; g_x2[b][t] = x2;
        g_ar[b][t] = (y2 - y1) * (x2 - x1);
        g_sc[b][t] = score;
    }
}

// ================= Kernel B: forward suppression bit-matrix =================
// grid = (94 col_blocks, 47 row_blocks(128 rows), 16 batches), 64 threads.
// Each thread owns 2 rows (i, i+64); computes u64 of "row suppresses col"
// bits for 64 columns; self/lower bits masked at the end.
__global__ __launch_bounds__(64)
void iou_matrix_kernel()
{
    const int cb = blockIdx.x;
    const int rb = blockIdx.y;
    if (cb < rb * 2) return;               // no column j > any row i here
    const int b   = blockIdx.z;
    const int tid = threadIdx.x;

    __shared__ float4 cbox[64];
    __shared__ float  care[64];

    const int j0 = cb * 64;
    {
        int j = j0 + tid;
        if (j < PRE_NMS) {
            cbox[tid] = make_float4(g_y1[b][j], g_x1[b][j], g_y2[b][j], g_x2[b][j]);
            care[tid] = g_ar[b][j];
        } else {
            cbox[tid] = make_float4(0.f, 0.f, 0.f, 0.f);   // inter=0 -> never hits
            care[tid] = 0.f;
        }
    }
    __syncthreads();

    float ry1[2], rx1[2], ry2[2], rx2[2], rar[2];
    u64 bits[2] = {0ull, 0ull};
    bool act[2];
    int  irow[2];
    #pragma unroll
    for (int r = 0; r < 2; r++) {
        int i = rb * 128 + r * 64 + tid;
        irow[r] = i;
        act[r] = (i < PRE_NMS);
        int ii = act[r] ? i : 0;
        ry1[r] = g_y1[b][ii]; rx1[r] = g_x1[b][ii];
        ry2[r] = g_y2[b][ii]; rx2[r] = g_x2[b][ii];
        rar[r] = g_ar[b][ii];
    }

    #pragma unroll 8
    for (int j = 0; j < 64; j++) {
        float4 c4 = cbox[j];
        float  ca = care[j];
        #pragma unroll
        for (int r = 0; r < 2; r++) {
            float ih = fmaxf(fminf(ry2[r], c4.z) - fmaxf(ry1[r], c4.x), 0.0f);
            float iw = fmaxf(fminf(rx2[r], c4.w) - fmaxf(rx1[r], c4.y), 0.0f);
            float inter = ih * iw;
            float d = rar[r] + ca - inter + 1e-8f;   // exact reference op order
            float diff = fmaf(-IOU_THR, d, inter);   // inter - 0.7*d
            bool hit = diff > 0.0f;
            if (fabsf(diff) <= 1e-5f * d)            // rare: exact IEEE decision
                hit = (inter / d) > IOU_THR;
            if (hit) bits[r] |= (1ull << j);
        }
    }

    #pragma unroll
    for (int r = 0; r < 2; r++) {
        if (act[r]) {
            int dlt = irow[r] - j0;
            u64 m = (dlt < 0) ? ~0ull : ((dlt >= 63) ? 0ull : (~0ull << (dlt + 1)));
            g_masks[b][cb][irow[r]] = bits[r] & m;
        }
    }
}

// ================= Kernel C: greedy bit-reduce + output ====================
// 128 threads: threads 0..93 own suppression word `rem` in a register.
__global__ __launch_bounds__(128, 1)
void nms_reduce_kernel(float* __restrict__ out)
{
    const int b   = blockIdx.x;
    const int tid = threadIdx.x;

    __shared__ u64 s_diag[64];
    __shared__ u64 s_remc;
    __shared__ int s_rows[64];
    __shared__ int s_nk;

    float* ob = out + (size_t)b * POST_NMS * 4;
    float* os = out + (size_t)BATCH * POST_NMS * 4 + (size_t)b * POST_NMS;

    for (int t = tid; t < POST_NMS * 4; t += 128) ob[t] = 0.0f;
    for (int t = tid; t < POST_NMS; t += 128)     os[t] = 0.0f;

    u64 rem = 0ull;
    if (tid < 64) s_diag[tid] = g_masks[b][0][tid];
    if (tid == 0) s_remc = 0ull;
    __syncthreads();

    int cnt = 0;
    for (int c = 0; c < NW; c++) {
        // resolve this 64-row chunk serially (iterate set bits of alive)
        if (tid == 0) {
            int lim = PRE_NMS - c * 64;             // >= 1 (94*64 = 6016 > 6000)
            u64 alive = ~s_remc;
            if (lim < 64) alive &= ((1ull << lim) - 1ull);
            int nk = 0, cc = cnt;
            while (alive && cc < POST_NMS) {
                int i = __ffsll((long long)alive) - 1;
                s_rows[nk++] = c * 64 + i;
                cc++;
                alive &= ~(s_diag[i] | (1ull << i));
            }
            s_nk = nk;
        }
        __syncthreads();
        const int nk = s_nk;

        // emit kept boxes (rank = cnt + position)
        if (tid < nk) {
            int r    = s_rows[tid];
            int rank = cnt + tid;
            ob[rank * 4 + 0] = fminf(fmaxf(g_y1[b][r], 0.0f), 1.0f);
            ob[rank * 4 + 1] = fminf(fmaxf(g_x1[b][r], 0.0f), 1.0f);
            ob[rank * 4 + 2] = fminf(fmaxf(g_y2[b][r], 0.0f), 1.0f);
            ob[rank * 4 + 3] = fminf(fmaxf(g_x2[b][r], 0.0f), 1.0f);
            os[rank] = g_sc[b][r];
        }

        // owners OR kept rows' masks into their register word
        if (tid < NW && tid > c) {
            #pragma unroll 4
            for (int m = 0; m < nk; m++) rem |= g_masks[b][tid][s_rows[m]];
        }

        // prefetch next chunk's diagonal words
        if (c + 1 < NW && tid >= 64) {
            int row = (c + 1) * 64 + (tid - 64);
            s_diag[tid - 64] = (row < PRE_NMS) ? g_masks[b][c + 1][row] : 0ull;
        }

        // publish next chunk's suppression word (after this thread's OR)
        if (tid == c + 1) s_remc = rem;

        cnt += nk;
        __syncthreads();
        if (cnt >= POST_NMS) break;
    }
}

// ============================== launch =====================================
extern "C" void kernel_launch(void* const* d_in, const int* in_sizes, int n_in,
                              void* d_out, int out_size) {
    const float* deltas  = (const float*)d_in[0];  // [16,31,31,36]
    const float* probs   = (const float*)d_in[1];  // [16,31,31,9]
    const float* anchors = (const float*)d_in[2];  // [8649,4]
    float* out = (float*)d_out;

    cudaFuncSetAttribute(sort_decode_kernel,
                         cudaFuncAttributeMaxDynamicSharedMemorySize, A_SMEM_TOTAL);

    sort_decode_kernel<<<BATCH, 1024, A_SMEM_TOTAL>>>(deltas, probs, anchors);
    iou_matrix_kernel<<<dim3(NW, 47, BATCH), 64>>>();
    nms_reduce_kernel<<<BATCH, 128>>>(out);
}

// round 4
// speedup vs baseline: 5.6845x; 1.0204x over previous
#include <cuda_runtime.h>
#include <cuda_bf16.h>
#include <cstdint>

#define IMG_N_ANC   8649      // 31*31*9
#define SORT_N      16384
#define SEL_N       8192
#define PRE_NMS     6000
#define POST_NMS    1500
#define IOU_THR     0.7f
#define BATCH       16
#define NW          94        // 94 u64 words cover 6016 >= 6000 cols
#define NWP         96        // padded row stride (768 B: line-friendly)
#define NPAD        6016
#define NBIN        2048

typedef unsigned long long u64;

// ---------------- device scratch (static; no allocations) ----------------
// row-major masks: g_masks[b][row][word]  (word w holds cols w*64..w*64+63)
__device__ u64   g_masks[BATCH][NPAD][NWP];   // ~73.9 MB
__device__ float g_y1[BATCH][NPAD];
__device__ float g_x1[BATCH][NPAD];
__device__ float g_y2[BATCH][NPAD];
__device__ float g_x2[BATCH][NPAD];
__device__ float g_ar[BATCH][NPAD];
__device__ float g_sc[BATCH][NPAD];

// ---------- descending bitonic sort, register-tiled (tile = 16 keys) -------
__device__ __forceinline__ void bitonic_sort_desc(u64* keys, int n, int tid, int nt)
{
    const int tiles = n >> 4;

    // mega pass: k = 2..16 entirely inside each 16-key tile (no barriers)
    for (int t = tid; t < tiles; t += nt) {
        const int base = t << 4;
        u64 r[16];
        #pragma unroll
        for (int e = 0; e < 16; e++) r[e] = keys[base + e];
        #pragma unroll
        for (int k = 2; k <= 16; k <<= 1) {
            #pragma unroll
            for (int j = k >> 1; j > 0; j >>= 1) {
                #pragma unroll
                for (int e = 0; e < 16; e++) {
                    if (!(e & j)) {
                        bool dir = (((base + e) & k) == 0);
                        u64 a = r[e], c = r[e | j];
                        if ((a < c) == dir) { r[e] = c; r[e | j] = a; }
                    }
                }
            }
        }
        #pragma unroll
        for (int e = 0; e < 16; e++) keys[base + e] = r[e];
    }
    __syncthreads();

    for (int k = 32; k <= n; k <<= 1) {
        // smem stages: j = k/2 .. 16 (pair-enumerated, every iter does work)
        for (int j = k >> 1; j >= 16; j >>= 1) {
            const int half = n >> 1;
            for (int p = tid; p < half; p += nt) {
                int i  = ((p & ~(j - 1)) << 1) | (p & (j - 1));
                int ix = i + j;
                u64 a = keys[i], c = keys[ix];
                bool dir = ((i & k) == 0);
                if ((a < c) == dir) { keys[i] = c; keys[ix] = a; }
            }
            __syncthreads();
        }
        // register tail: j = 8,4,2,1 (dir uniform per tile since k >= 32)
        for (int t = tid; t < tiles; t += nt) {
            const int base = t << 4;
            const bool dir = ((base & k) == 0);
            u64 r[16];
            #pragma unroll
            for (int e = 0; e < 16; e++) r[e] = keys[base + e];
            #pragma unroll
            for (int j = 8; j > 0; j >>= 1) {
                #pragma unroll
                for (int e = 0; e < 16; e++) {
                    if (!(e & j)) {
                        u64 a = r[e], c = r[e | j];
                        if ((a < c) == dir) { r[e] = c; r[e | j] = a; }
                    }
                }
            }
            #pragma unroll
            for (int e = 0; e < 16; e++) keys[base + e] = r[e];
        }
        __syncthreads();
    }
}

// ================= Kernel A: select + sort + decode top-6000 =================
#define A_OFF_KSORT   (SORT_N * 8)                 // 131072
#define A_OFF_HIST    (A_OFF_KSORT + SEL_N * 8)    // 196608
#define A_OFF_CTL     (A_OFF_HIST + NBIN * 4)      // 204800
#define A_SMEM_TOTAL  (A_OFF_CTL + 16)
#define A_NT          512

__global__ __launch_bounds__(A_NT, 1)
void sort_decode_kernel(const float* __restrict__ deltas,   // [B,N,4]
                        const float* __restrict__ probs,    // [B,N]
                        const float* __restrict__ anchors)  // [N,4]
{
    extern __shared__ char smem[];
    u64* keys_in   = (u64*)smem;
    u64* keys_sort = (u64*)(smem + A_OFF_KSORT);
    unsigned int* hist = (unsigned int*)(smem + A_OFF_HIST);
    int* s_bint  = (int*)(smem + A_OFF_CTL);
    int* s_total = (int*)(smem + A_OFF_CTL + 4);
    int* s_cnt   = (int*)(smem + A_OFF_CTL + 8);

    const int b   = blockIdx.x;
    const int tid = threadIdx.x;
    const int nt  = A_NT;

    for (int i = tid; i < NBIN; i += nt) hist[i] = 0u;
    if (tid == 0) *s_cnt = 0;
    __syncthreads();

    // load keys + histogram (bin = top 13 bits of the u64 key)
    const float* pb = probs + (size_t)b * IMG_N_ANC;
    for (int i = tid; i < SORT_N; i += nt) {
        u64 k = 0ull;
        if (i < IMG_N_ANC) {
            unsigned int bits = __float_as_uint(pb[i]);  // [0,1): bit order == value order
            k = ((u64)bits << 32) | (u64)(0xFFFFFFFFu - (unsigned)i);
            atomicAdd(&hist[(unsigned)(k >> 51)], 1u);
        }
        keys_in[i] = k;
    }
    __syncthreads();

    // suffix scan over bins (descending value order) — one warp
    if (tid < 32) {
        const int lane = tid;
        int part = 0;
        #pragma unroll 8
        for (int q = 0; q < 64; q++) part += (int)hist[NBIN - 1 - (lane * 64 + q)];
        int inc = part;
        #pragma unroll
        for (int off = 1; off < 32; off <<= 1) {
            int v = __shfl_up_sync(0xFFFFFFFFu, inc, off);
            if (lane >= off) inc += v;
        }
        int run = inc - part;   // exclusive
        for (int q = 0; q < 64; q++) {
            int v = NBIN - 1 - (lane * 64 + q);
            int h = (int)hist[v];
            run += h;
            if (run >= PRE_NMS && run - h < PRE_NMS) { *s_bint = v; *s_total = run; }
        }
    }
    __syncthreads();

    const int bint  = *s_bint;
    const int total = *s_total;
    const bool mainpath = (total <= SEL_N);

    if (mainpath) {
        for (int i = tid; i < IMG_N_ANC; i += nt) {
            u64 k = keys_in[i];
            if ((int)(unsigned)(k >> 51) >= bint) {
                int pos = atomicAdd(s_cnt, 1);
                keys_sort[pos] = k;
            }
        }
        for (int i = total + tid; i < SEL_N; i += nt) keys_sort[i] = 0ull;
        __syncthreads();
        bitonic_sort_desc(keys_sort, SEL_N, tid, nt);
    } else {
        bitonic_sort_desc(keys_in, SORT_N, tid, nt);   // fallback (never expected)
    }

    const u64* sorted = mainpath ? keys_sort : keys_in;

    // decode top-6000 to global SoA
    const float* db = deltas + (size_t)b * IMG_N_ANC * 4;
    for (int t = tid; t < PRE_NMS; t += nt) {
        u64 key = sorted[t];
        unsigned int idx = 0xFFFFFFFFu - (unsigned int)(key & 0xFFFFFFFFull);
        float score = __uint_as_float((unsigned int)(key >> 32));

        float a0 = anchors[idx * 4 + 0];
        float a1 = anchors[idx * 4 + 1];
        float a2 = anchors[idx * 4 + 2];
        float a3 = anchors[idx * 4 + 3];
        float d0 = db[(size_t)idx * 4 + 0] * 0.1f;
        float d1 = db[(size_t)idx * 4 + 1] * 0.1f;
        float d2 = db[(size_t)idx * 4 + 2] * 0.2f;
        float d3 = db[(size_t)idx * 4 + 3] * 0.2f;

        float anc_h = a2 - a0;
        float anc_w = a3 - a1;
        float ctr_y = a0 + 0.5f * anc_h;
        float ctr_x = a1 + 0.5f * anc_w;
        float bh = expf(d2) * anc_h;
        float bw = expf(d3) * anc_w;
        float bcy = d0 * anc_h + ctr_y;
        float bcx = d1 * anc_w + ctr_x;
        float y1 = bcy - 0.5f * bh;
        float x1 = bcx - 0.5f * bw;
        float y2 = y1 + bh;
        float x2 = x1 + bw;

        g_y1[b][t] = y1; g_x1[b][t] = x1;
        g_y2[b][t] = y2; g_x2[b][t] = x2;
        g_ar[b][t] = (y2 - y1) * (x2 - x1);
        g_sc[b][t] = score;
    }
}

// ================= Kernel B: forward suppression bit-matrix =================
// grid = (94 col_blocks, 24 row_blocks(256 rows), 16 batches), 64 threads.
// Each thread owns 4 rows; computes u64 of "row suppresses col" bits for the
// block's 64 columns; self/sub-diagonal bits masked at the end.
// Write g_masks[b][row][cb]. Needed (row,word) pairs: word >= row/64, i.e.
// blocks with cb >= 4*rb; others rejected.
__global__ __launch_bounds__(64)
void iou_matrix_kernel()
{
    const int cb = blockIdx.x;
    const int rb = blockIdx.y;
    if (cb < rb * 4) return;
    const int b   = blockIdx.z;
    const int tid = threadIdx.x;

    __shared__ float4 cbox[64];
    __shared__ float  care[64];

    const int j0 = cb * 64;
    {
        int j = j0 + tid;
        if (j < PRE_NMS) {
            cbox[tid] = make_float4(g_y1[b][j], g_x1[b][j], g_y2[b][j], g_x2[b][j]);
            care[tid] = g_ar[b][j];
        } else {
            cbox[tid] = make_float4(0.f, 0.f, 0.f, 0.f);   // inter=0 -> never hits
            care[tid] = 0.f;
        }
    }
    __syncthreads();

    float ry1[4], rx1[4], ry2[4], rx2[4], rar[4];
    u64 bits[4] = {0ull, 0ull, 0ull, 0ull};
    int  irow[4];
    #pragma unroll
    for (int r = 0; r < 4; r++) {
        int i = rb * 256 + r * 64 + tid;
        irow[r] = i;
        int ii = (i < PRE_NMS) ? i : 0;
        ry1[r] = g_y1[b][ii]; rx1[r] = g_x1[b][ii];
        ry2[r] = g_y2[b][ii]; rx2[r] = g_x2[b][ii];
        rar[r] = g_ar[b][ii];
    }

    #pragma unroll 8
    for (int j = 0; j < 64; j++) {
        float4 c4 = cbox[j];
        float  ca = care[j];
        #pragma unroll
        for (int r = 0; r < 4; r++) {
            float ih = fmaxf(fminf(ry2[r], c4.z) - fmaxf(ry1[r], c4.x), 0.0f);
            float iw = fmaxf(fminf(rx2[r], c4.w) - fmaxf(rx1[r], c4.y), 0.0f);
            float inter = ih * iw;
            float d = rar[r] + ca - inter + 1e-8f;   // exact reference op order
            float diff = fmaf(-IOU_THR, d, inter);   // inter - 0.7*d
            bool hit = diff > 0.0f;
            if (fabsf(diff) <= 1e-5f * d)            // rare: exact IEEE decision
                hit = (inter / d) > IOU_THR;
            if (hit) bits[r] |= (1ull << j);
        }
    }

    #pragma unroll
    for (int r = 0; r < 4; r++) {
        int i = irow[r];
        if (i < PRE_NMS) {
            int dlt = i - j0;   // keep only cols j > i
            u64 m = (dlt < 0) ? ~0ull : ((dlt >= 63) ? 0ull : (~0ull << (dlt + 1)));
            g_masks[b][i][cb] = bits[r] & m;
        }
    }
}

// ================= Kernel C: greedy bit-reduce + output ====================
// 128 threads: threads 0..93 own suppression word `rem` in a register.
// Owner loads g_masks[b][row][tid] are coalesced (row-major layout).
__global__ __launch_bounds__(128, 1)
void nms_reduce_kernel(float* __restrict__ out)
{
    const int b   = blockIdx.x;
    const int tid = threadIdx.x;

    __shared__ u64 s_diag[64];
    __shared__ u64 s_remc;
    __shared__ int s_rows[64];
    __shared__ int s_nk;

    float* ob = out + (size_t)b * POST_NMS * 4;
    float* os = out + (size_t)BATCH * POST_NMS * 4 + (size_t)b * POST_NMS;

    for (int t = tid; t < POST_NMS * 4; t += 128) ob[t] = 0.0f;
    for (int t = tid; t < POST_NMS; t += 128)     os[t] = 0.0f;

    u64 rem = 0ull;
    if (tid < 64) s_diag[tid] = g_masks[b][tid][0];
    if (tid == 0) s_remc = 0ull;
    __syncthreads();

    int cnt = 0;
    for (int c = 0; c < NW; c++) {
        // resolve this 64-row chunk serially (iterate set bits of alive)
        if (tid == 0) {
            int lim = PRE_NMS - c * 64;             // >= 1 (94*64 = 6016 > 6000)
            u64 alive = ~s_remc;
            if (lim < 64) alive &= ((1ull << lim) - 1ull);
            int nk = 0, cc = cnt;
            while (alive && cc < POST_NMS) {
                int i = __ffsll((long long)alive) - 1;
                s_rows[nk++] = c * 64 + i;
                cc++;
                alive &= ~(s_diag[i] | (1ull << i));
            }
            s_nk = nk;
        }
        __syncthreads();
        const int nk = s_nk;

        // emit kept boxes (rank = cnt + position)
        if (tid < nk) {
            int r    = s_rows[tid];
            int rank = cnt + tid;
            ob[rank * 4 + 0] = fminf(fmaxf(g_y1[b][r], 0.0f), 1.0f);
            ob[rank * 4 + 1] = fminf(fmaxf(g_x1[b][r], 0.0f), 1.0f);
            ob[rank * 4 + 2] = fminf(fmaxf(g_y2[b][r], 0.0f), 1.0f);
            ob[rank * 4 + 3] = fminf(fmaxf(g_x2[b][r], 0.0f), 1.0f);
            os[rank] = g_sc[b][r];
        }

        // owners OR kept rows' masks into their register word (coalesced)
        if (tid < NW && tid > c) {
            #pragma unroll 4
            for (int m = 0; m < nk; m++) rem |= g_masks[b][s_rows[m]][tid];
        }

        // prefetch next chunk's diagonal words
        if (c + 1 < NW && tid >= 64) {
            int row = (c + 1) * 64 + (tid - 64);
            s_diag[tid - 64] = (row < PRE_NMS) ? g_masks[b][row][c + 1] : 0ull;
        }

        // publish next chunk's suppression word (after this thread's OR)
        if (tid == c + 1) s_remc = rem;

        cnt += nk;
        __syncthreads();
        if (cnt >= POST_NMS) break;
    }
}

// ============================== launch =====================================
extern "C" void kernel_launch(void* const* d_in, const int* in_sizes, int n_in,
                              void* d_out, int out_size) {
    const float* deltas  = (const float*)d_in[0];  // [16,31,31,36]
    const float* probs   = (const float*)d_in[1];  // [16,31,31,9]
    const float* anchors = (const float*)d_in[2];  // [8649,4]
    float* out = (float*)d_out;

    cudaFuncSetAttribute(sort_decode_kernel,
                         cudaFuncAttributeMaxDynamicSharedMemorySize, A_SMEM_TOTAL);

    sort_decode_kernel<<<BATCH, A_NT, A_SMEM_TOTAL>>>(deltas, probs, anchors);
    iou_matrix_kernel<<<dim3(NW, 24, BATCH), 64>>>();
    nms_reduce_kernel<<<BATCH, 128>>>(out);
}

// round 5
// speedup vs baseline: 6.7307x; 1.1840x over previous
#include <cuda_runtime.h>
#include <cuda_bf16.h>
#include <cstdint>

#define IMG_N_ANC   8649      // 31*31*9
#define SORT_N      16384
#define SEL_N       8192
#define PRE_NMS     6000
#define POST_NMS    1500
#define IOU_THR     0.7f
#define BATCH       16
#define NW          94        // 94 u64 words cover 6016 >= 6000 cols
#define NWP         96        // padded row stride (768 B)
#define NPAD        6016
#define NBIN        2048

typedef unsigned long long u64;

// ---------------- device scratch (static; no allocations) ----------------
// row-major masks: g_masks[b][row][word]  (word w holds cols w*64..w*64+63)
__device__ u64   g_masks[BATCH][NPAD][NWP];   // ~73.9 MB
__device__ float g_y1[BATCH][NPAD];
__device__ float g_x1[BATCH][NPAD];
__device__ float g_y2[BATCH][NPAD];
__device__ float g_x2[BATCH][NPAD];
__device__ float g_ar[BATCH][NPAD];
__device__ float g_sc[BATCH][NPAD];

// ---------- descending bitonic sort, register-tiled (tile = 8 keys) --------
// n power of two >= 16. 8 u64 = 16 regs per live tile: no spills at 1024 thr.
__device__ __forceinline__ void bitonic_sort_desc(u64* keys, int n, int tid, int nt)
{
    const int tiles = n >> 3;

    // mega pass: k = 2,4,8 entirely inside each 8-key tile (no barriers)
    for (int t = tid; t < tiles; t += nt) {
        const int base = t << 3;
        u64 r[8];
        #pragma unroll
        for (int e = 0; e < 8; e++) r[e] = keys[base + e];
        #pragma unroll
        for (int k = 2; k <= 8; k <<= 1) {
            #pragma unroll
            for (int j = k >> 1; j > 0; j >>= 1) {
                #pragma unroll
                for (int e = 0; e < 8; e++) {
                    if (!(e & j)) {
                        bool dir = (((base + e) & k) == 0);
                        u64 a = r[e], c = r[e | j];
                        if ((a < c) == dir) { r[e] = c; r[e | j] = a; }
                    }
                }
            }
        }
        #pragma unroll
        for (int e = 0; e < 8; e++) keys[base + e] = r[e];
    }
    __syncthreads();

    for (int k = 16; k <= n; k <<= 1) {
        // smem stages: j = k/2 .. 8 (pair-enumerated, every iter does work)
        for (int j = k >> 1; j >= 8; j >>= 1) {
            const int half = n >> 1;
            for (int p = tid; p < half; p += nt) {
                int i  = ((p & ~(j - 1)) << 1) | (p & (j - 1));
                int ix = i + j;
                u64 a = keys[i], c = keys[ix];
                bool dir = ((i & k) == 0);
                if ((a < c) == dir) { keys[i] = c; keys[ix] = a; }
            }
            __syncthreads();
        }
        // register tail: j = 4,2,1 (dir uniform per tile since k >= 16)
        for (int t = tid; t < tiles; t += nt) {
            const int base = t << 3;
            const bool dir = ((base & k) == 0);
            u64 r[8];
            #pragma unroll
            for (int e = 0; e < 8; e++) r[e] = keys[base + e];
            #pragma unroll
            for (int j = 4; j > 0; j >>= 1) {
                #pragma unroll
                for (int e = 0; e < 8; e++) {
                    if (!(e & j)) {
                        u64 a = r[e], c = r[e | j];
                        if ((a < c) == dir) { r[e] = c; r[e | j] = a; }
                    }
                }
            }
            #pragma unroll
            for (int e = 0; e < 8; e++) keys[base + e] = r[e];
        }
        __syncthreads();
    }
}

// ================= Kernel A: select + sort + decode top-6000 =================
#define A_OFF_KSORT   (SORT_N * 8)                 // 131072
#define A_OFF_HIST    (A_OFF_KSORT + SEL_N * 8)    // 196608
#define A_OFF_CTL     (A_OFF_HIST + NBIN * 4)      // 204800
#define A_SMEM_TOTAL  (A_OFF_CTL + 16)
#define A_NT          1024

__global__ __launch_bounds__(A_NT, 1)
void sort_decode_kernel(const float* __restrict__ deltas,   // [B,N,4]
                        const float* __restrict__ probs,    // [B,N]
                        const float* __restrict__ anchors)  // [N,4]
{
    extern __shared__ char smem[];
    u64* keys_in   = (u64*)smem;
    u64* keys_sort = (u64*)(smem + A_OFF_KSORT);
    unsigned int* hist = (unsigned int*)(smem + A_OFF_HIST);
    int* s_bint  = (int*)(smem + A_OFF_CTL);
    int* s_total = (int*)(smem + A_OFF_CTL + 4);
    int* s_cnt   = (int*)(smem + A_OFF_CTL + 8);

    const int b   = blockIdx.x;
    const int tid = threadIdx.x;
    const int nt  = A_NT;

    for (int i = tid; i < NBIN; i += nt) hist[i] = 0u;
    if (tid == 0) *s_cnt = 0;
    __syncthreads();

    // load keys + histogram (bin = top 13 bits of the u64 key)
    const float* pb = probs + (size_t)b * IMG_N_ANC;
    for (int i = tid; i < SORT_N; i += nt) {
        u64 k = 0ull;
        if (i < IMG_N_ANC) {
            unsigned int bits = __float_as_uint(pb[i]);  // [0,1): bit order == value order
            k = ((u64)bits << 32) | (u64)(0xFFFFFFFFu - (unsigned)i);
            atomicAdd(&hist[(unsigned)(k >> 51)], 1u);
        }
        keys_in[i] = k;
    }
    __syncthreads();

    // suffix scan over bins (descending value order) — one warp
    if (tid < 32) {
        const int lane = tid;
        int part = 0;
        #pragma unroll 8
        for (int q = 0; q < 64; q++) part += (int)hist[NBIN - 1 - (lane * 64 + q)];
        int inc = part;
        #pragma unroll
        for (int off = 1; off < 32; off <<= 1) {
            int v = __shfl_up_sync(0xFFFFFFFFu, inc, off);
            if (lane >= off) inc += v;
        }
        int run = inc - part;   // exclusive
        for (int q = 0; q < 64; q++) {
            int v = NBIN - 1 - (lane * 64 + q);
            int h = (int)hist[v];
            run += h;
            if (run >= PRE_NMS && run - h < PRE_NMS) { *s_bint = v; *s_total = run; }
        }
    }
    __syncthreads();

    const int bint  = *s_bint;
    const int total = *s_total;
    const bool mainpath = (total <= SEL_N);

    if (mainpath) {
        for (int i = tid; i < IMG_N_ANC; i += nt) {
            u64 k = keys_in[i];
            if ((int)(unsigned)(k >> 51) >= bint) {
                int pos = atomicAdd(s_cnt, 1);
                keys_sort[pos] = k;
            }
        }
        for (int i = total + tid; i < SEL_N; i += nt) keys_sort[i] = 0ull;
        __syncthreads();
        bitonic_sort_desc(keys_sort, SEL_N, tid, nt);
    } else {
        bitonic_sort_desc(keys_in, SORT_N, tid, nt);   // fallback (never expected)
    }

    const u64* sorted = mainpath ? keys_sort : keys_in;

    // decode top-6000 to global SoA
    const float* db = deltas + (size_t)b * IMG_N_ANC * 4;
    for (int t = tid; t < PRE_NMS; t += nt) {
        u64 key = sorted[t];
        unsigned int idx = 0xFFFFFFFFu - (unsigned int)(key & 0xFFFFFFFFull);
        float score = __uint_as_float((unsigned int)(key >> 32));

        float a0 = anchors[idx * 4 + 0];
        float a1 = anchors[idx * 4 + 1];
        float a2 = anchors[idx * 4 + 2];
        float a3 = anchors[idx * 4 + 3];
        float d0 = db[(size_t)idx * 4 + 0] * 0.1f;
        float d1 = db[(size_t)idx * 4 + 1] * 0.1f;
        float d2 = db[(size_t)idx * 4 + 2] * 0.2f;
        float d3 = db[(size_t)idx * 4 + 3] * 0.2f;

        float anc_h = a2 - a0;
        float anc_w = a3 - a1;
        float ctr_y = a0 + 0.5f * anc_h;
        float ctr_x = a1 + 0.5f * anc_w;
        float bh = expf(d2) * anc_h;
        float bw = expf(d3) * anc_w;
        float bcy = d0 * anc_h + ctr_y;
        float bcx = d1 * anc_w + ctr_x;
        float y1 = bcy - 0.5f * bh;
        float x1 = bcx - 0.5f * bw;
        float y2 = y1 + bh;
        float x2 = x1 + bw;

        g_y1[b][t] = y1; g_x1[b][t] = x1;
        g_y2[b][t] = y2; g_x2[b][t] = x2;
        g_ar[b][t] = (y2 - y1) * (x2 - x1);
        g_sc[b][t] = score;
    }
}

// ================= Kernel B: forward suppression bit-matrix =================
// grid = (94 col_blocks, 24 row_blocks(256 rows), 16 batches), 64 threads.
__global__ __launch_bounds__(64)
void iou_matrix_kernel()
{
    const int cb = blockIdx.x;
    const int rb = blockIdx.y;
    if (cb < rb * 4) return;
    const int b   = blockIdx.z;
    const int tid = threadIdx.x;

    __shared__ float4 cbox[64];
    __shared__ float  care[64];

    const int j0 = cb * 64;
    {
        int j = j0 + tid;
        if (j < PRE_NMS) {
            cbox[tid] = make_float4(g_y1[b][j], g_x1[b][j], g_y2[b][j], g_x2[b][j]);
            care[tid] = g_ar[b][j];
        } else {
            cbox[tid] = make_float4(0.f, 0.f, 0.f, 0.f);   // inter=0 -> never hits
            care[tid] = 0.f;
        }
    }
    __syncthreads();

    float ry1[4], rx1[4], ry2[4], rx2[4], rar[4];
    u64 bits[4] = {0ull, 0ull, 0ull, 0ull};
    int  irow[4];
    #pragma unroll
    for (int r = 0; r < 4; r++) {
        int i = rb * 256 + r * 64 + tid;
        irow[r] = i;
        int ii = (i < PRE_NMS) ? i : 0;
        ry1[r] = g_y1[b][ii]; rx1[r] = g_x1[b][ii];
        ry2[r] = g_y2[b][ii]; rx2[r] = g_x2[b][ii];
        rar[r] = g_ar[b][ii];
    }

    #pragma unroll 8
    for (int j = 0; j < 64; j++) {
        float4 c4 = cbox[j];
        float  ca = care[j];
        #pragma unroll
        for (int r = 0; r < 4; r++) {
            float ih = fmaxf(fminf(ry2[r], c4.z) - fmaxf(ry1[r], c4.x), 0.0f);
            float iw = fmaxf(fminf(rx2[r], c4.w) - fmaxf(rx1[r], c4.y), 0.0f);
            float inter = ih * iw;
            float d = rar[r] + ca - inter + 1e-8f;   // exact reference op order
            float diff = fmaf(-IOU_THR, d, inter);   // inter - 0.7*d
            bool hit = diff > 0.0f;
            if (fabsf(diff) <= 1e-5f * d)            // rare: exact IEEE decision
                hit = (inter / d) > IOU_THR;
            if (hit) bits[r] |= (1ull << j);
        }
    }

    #pragma unroll
    for (int r = 0; r < 4; r++) {
        int i = irow[r];
        if (i < PRE_NMS) {
            int dlt = i - j0;   // keep only cols j > i
            u64 m = (dlt < 0) ? ~0ull : ((dlt >= 63) ? 0ull : (~0ull << (dlt + 1)));
            g_masks[b][i][cb] = bits[r] & m;
        }
    }
}

// ================= Kernel C: greedy bit-reduce + output ====================
// 512 threads. Threads 0..375: tid = 4*w + sub co-own word w (sub ORs kept
// rows m = sub, sub+4, ...). The 4 partials of next chunk's word are
// published to s_pub; thread 0 combines them at resolve. Threads 448..511
// prefetch the next diagonal word block.
#define C_NT 512

__global__ __launch_bounds__(C_NT, 1)
void nms_reduce_kernel(float* __restrict__ out)
{
    const int b   = blockIdx.x;
    const int tid = threadIdx.x;

    __shared__ u64 s_diag[64];
    __shared__ u64 s_pub[4];
    __shared__ int s_rows[64];
    __shared__ int s_nk;

    float* ob = out + (size_t)b * POST_NMS * 4;
    float* os = out + (size_t)BATCH * POST_NMS * 4 + (size_t)b * POST_NMS;

    for (int t = tid; t < POST_NMS * 4; t += C_NT) ob[t] = 0.0f;
    for (int t = tid; t < POST_NMS; t += C_NT)     os[t] = 0.0f;

    const int w   = tid >> 2;        // owned word (valid when tid < 376)
    const int sub = tid & 3;
    u64 rem = 0ull;

    if (tid >= 448) s_diag[tid - 448] = g_masks[b][tid - 448][0];
    if (tid < 4) s_pub[tid] = 0ull;
    __syncthreads();

    int cnt = 0;
    for (int c = 0; c < NW; c++) {
        // resolve this 64-row chunk serially (iterate set bits of alive)
        if (tid == 0) {
            u64 remc = s_pub[0] | s_pub[1] | s_pub[2] | s_pub[3];
            int lim = PRE_NMS - c * 64;             // >= 1 (94*64 = 6016 > 6000)
            u64 alive = ~remc;
            if (lim < 64) alive &= ((1ull << lim) - 1ull);
            int nk = 0, cc = cnt;
            while (alive && cc < POST_NMS) {
                int i = __ffsll((long long)alive) - 1;
                s_rows[nk++] = c * 64 + i;
                cc++;
                alive &= ~(s_diag[i] | (1ull << i));
            }
            s_nk = nk;
        }
        __syncthreads();
        const int nk = s_nk;

        // emit kept boxes (rank = cnt + position)
        if (tid < nk) {
            int r    = s_rows[tid];
            int rank = cnt + tid;
            ob[rank * 4 + 0] = fminf(fmaxf(g_y1[b][r], 0.0f), 1.0f);
            ob[rank * 4 + 1] = fminf(fmaxf(g_x1[b][r], 0.0f), 1.0f);
            ob[rank * 4 + 2] = fminf(fmaxf(g_y2[b][r], 0.0f), 1.0f);
            ob[rank * 4 + 3] = fminf(fmaxf(g_x2[b][r], 0.0f), 1.0f);
            os[rank] = g_sc[b][r];
        }

        // co-owners OR kept rows' masks into their partial register word
        if (tid < 376 && w > c) {
            #pragma unroll 4
            for (int m = sub; m < nk; m += 4) rem |= g_masks[b][s_rows[m]][w];
        }

        // prefetch next chunk's diagonal words
        if (c + 1 < NW && tid >= 448) {
            int row = (c + 1) * 64 + (tid - 448);
            s_diag[tid - 448] = (row < PRE_NMS) ? g_masks[b][row][c + 1] : 0ull;
        }

        // owners of next word publish their partials (after their OR above)
        if (tid < 376 && w == c + 1) s_pub[sub] = rem;

        cnt += nk;
        __syncthreads();
        if (cnt >= POST_NMS) break;
    }
}

// ============================== launch =====================================
extern "C" void kernel_launch(void* const* d_in, const int* in_sizes, int n_in,
                              void* d_out, int out_size) {
    const float* deltas  = (const float*)d_in[0];  // [16,31,31,36]
    const float* probs   = (const float*)d_in[1];  // [16,31,31,9]
    const float* anchors = (const float*)d_in[2];  // [8649,4]
    float* out = (float*)d_out;

    cudaFuncSetAttribute(sort_decode_kernel,
                         cudaFuncAttributeMaxDynamicSharedMemorySize, A_SMEM_TOTAL);

    sort_decode_kernel<<<BATCH, A_NT, A_SMEM_TOTAL>>>(deltas, probs, anchors);
    iou_matrix_kernel<<<dim3(NW, 24, BATCH), 64>>>();
    nms_reduce_kernel<<<BATCH, C_NT>>>(out);
}